// round 9
// baseline (speedup 1.0000x reference)
#include <cuda_runtime.h>
#include <math.h>
#include <stdint.h>

typedef unsigned long long ull;

// ---------------- problem constants ----------------
#define Bq   8
#define Cc   64
#define Hh   256
#define Ww   256
#define HWs  65536
#define CHW  4194304
#define RB   16          // CTAs per batch (= cluster size)
#define T_W  16
#define THREADS 256
#define RSTRD 18         // ull stride per channel row (banks: conflict-free)

// ---------------- cluster kernel smem map (bytes) ----------------
#define OFF_W     0
#define W_BYTES   (16*64*3*16)          // 49152: [g][cin][tap] float4 (couts 4g..4g+3)
#define OFF_D0    49152                 // row buf A: 64*18 ull = 9216
#define OFF_D1    58368                 // row buf B: 9216
#define OFF_HALO  67584                 // [par][side][64] ull = 2048
#define OFF_BAR   69632                 // 2 mbarriers
#define SMEM_BYTES 69648

// ---------------- f32x2 helpers ----------------
#define FMA2(acc, a, b) asm("fma.rn.f32x2 %0, %1, %2, %3;" : "=l"(acc) : "l"(a), "l"(b), "l"(acc))

__device__ __forceinline__ ull pack2(float lo, float hi) {
    ull r;
    asm("mov.b64 %0, {%1, %2};" : "=l"(r)
        : "r"(__float_as_uint(lo)), "r"(__float_as_uint(hi)));
    return r;
}
__device__ __forceinline__ void unpack2(ull v, float& lo, float& hi) {
    unsigned int a, b2;
    asm("mov.b64 {%0, %1}, %2;" : "=r"(a), "=r"(b2) : "l"(v));
    lo = __uint_as_float(a); hi = __uint_as_float(b2);
}

__device__ __forceinline__ float tanh_fast(float x) {
    float ax = fabsf(x);
    float e  = __expf(2.0f * ax);
    float t  = 1.0f - 2.0f / (e + 1.0f);
    return copysignf(t, x);
}

// ---------------- cluster / mbarrier PTX ----------------
__device__ __forceinline__ uint32_t smem_u32(const void* p) {
    uint32_t a;
    asm("{ .reg .u64 t; cvta.to.shared.u64 t, %1; cvt.u32.u64 %0, t; }" : "=r"(a) : "l"(p));
    return a;
}
__device__ __forceinline__ uint32_t mapa_rank(uint32_t laddr, uint32_t rank) {
    uint32_t r;
    asm("mapa.shared::cluster.u32 %0, %1, %2;" : "=r"(r) : "r"(laddr), "r"(rank));
    return r;
}
__device__ __forceinline__ void st_cluster_u64(uint32_t raddr, ull v) {
    asm volatile("st.shared::cluster.u64 [%0], %1;" :: "r"(raddr), "l"(v) : "memory");
}
__device__ __forceinline__ void arrive_cluster(uint32_t raddr) {
    asm volatile("mbarrier.arrive.release.cluster.shared::cluster.b64 _, [%0];"
                 :: "r"(raddr) : "memory");
}
__device__ __forceinline__ void mbar_init(uint32_t addr, unsigned int cnt) {
    asm volatile("mbarrier.init.shared.b64 [%0], %1;" :: "r"(addr), "r"(cnt) : "memory");
}
__device__ __forceinline__ void mbar_wait_cluster(uint32_t addr, int parity) {
    asm volatile(
        "{\n\t.reg .pred P;\n\t"
        "W%=:\n\t"
        "mbarrier.try_wait.parity.acquire.cluster.shared::cta.b64 P, [%0], %1;\n\t"
        "@!P bra W%=;\n\t}"
        :: "r"(addr), "r"(parity) : "memory");
}
__device__ __forceinline__ void cluster_sync_() {
    asm volatile("barrier.cluster.arrive.aligned;" ::: "memory");
    asm volatile("barrier.cluster.wait.aligned;" ::: "memory");
}

// publish this thread's 4 freshly-computed edge values to a neighbor's halo + arrive
__device__ __forceinline__ void publish(uint32_t sbase, int par, int side_slot,
                                        uint32_t rank, int c0,
                                        float y0, float y1, float y2, float y3)
{
    uint32_t loc = sbase + OFF_HALO + (unsigned)((par * 2 + side_slot) * 64 + c0) * 8u;
    uint32_t rem = mapa_rank(loc, rank);
    st_cluster_u64(rem + 0,  pack2(y0, y0));
    st_cluster_u64(rem + 8,  pack2(y1, y1));
    st_cluster_u64(rem + 16, pack2(y2, y2));
    st_cluster_u64(rem + 24, pack2(y3, y3));
    uint32_t rbar = mapa_rank(sbase + OFF_BAR + (unsigned)par * 8u, rank);
    arrive_cluster(rbar);
}

// ==================== cluster kernel ====================
__global__ void __launch_bounds__(THREADS, 1)
spatial_conv_cluster(const float* __restrict__ X,
                     const float* __restrict__ Wc,
                     const float* __restrict__ bc,
                     float* __restrict__ Y)
{
    extern __shared__ __align__(16) char smem[];
    float4* wMain = reinterpret_cast<float4*>(smem + OFF_W);
    ull*    d0    = reinterpret_cast<ull*>(smem + OFF_D0);
    ull*    d1    = reinterpret_cast<ull*>(smem + OFF_D1);
    ull*    sHalo = reinterpret_cast<ull*>(smem + OFF_HALO);

    const int tid = threadIdx.x;
    const int b   = blockIdx.x >> 4;
    const uint32_t r = blockIdx.x & 15;      // == cluster rank (cluster dims (16,1,1))
    const int w  = tid & 15;
    const int g  = tid >> 4;
    const int c0 = g * 4;
    const int wg = (int)r * T_W + w;
    const uint32_t sbase = smem_u32(smem);

    // ---- stage weights: wMain[(g*64+cin)*3+tap] = K_tap for couts 4g..4g+3 ----
    for (int idx = tid; idx < 16 * 64 * 3; idx += THREADS) {
        int gg  = idx / 192;
        int rem = idx - gg * 192;
        int cin = rem / 3;
        int tap = rem - cin * 3;
        float4 v;
        v.x = Wc[((4 * gg + 0) * Cc + cin) * 3 + tap];
        v.y = Wc[((4 * gg + 1) * Cc + cin) * 3 + tap];
        v.z = Wc[((4 * gg + 2) * Cc + cin) * 3 + tap];
        v.w = Wc[((4 * gg + 3) * Cc + cin) * 3 + tap];
        wMain[idx] = v;
    }
    // zero halos (edge CTAs read zeros on their missing side)
    for (int i = tid; i < 256; i += THREADS) sHalo[i] = 0ull;
    // init mbarriers: arrivals per phase = 16 per existing neighbor
    if (tid == 0) {
        unsigned int cnt = 16u * ((r > 0) + (r < 15));
        mbar_init(sbase + OFF_BAR + 0, cnt);
        mbar_init(sbase + OFF_BAR + 8, cnt);
    }
    __syncthreads();
    cluster_sync_();      // barriers visible cluster-wide before any remote arrive

    const float* Xb = X + b * CHW;
    float*       Yb = Y + b * CHW;

    const ull b01 = pack2(bc[c0 + 0], bc[c0 + 1]);
    const ull b23 = pack2(bc[c0 + 2], bc[c0 + 3]);

    // ---- row 0: Y[0] = X[0] ----
    {
        float y0 = Xb[(c0 + 0) * HWs + wg];
        float y1 = Xb[(c0 + 1) * HWs + wg];
        float y2 = Xb[(c0 + 2) * HWs + wg];
        float y3 = Xb[(c0 + 3) * HWs + wg];
        Yb[(c0 + 0) * HWs + wg] = y0;
        Yb[(c0 + 1) * HWs + wg] = y1;
        Yb[(c0 + 2) * HWs + wg] = y2;
        Yb[(c0 + 3) * HWs + wg] = y3;
        d0[(c0 + 0) * RSTRD + 1 + w] = pack2(y0, y0);
        d0[(c0 + 1) * RSTRD + 1 + w] = pack2(y1, y1);
        d0[(c0 + 2) * RSTRD + 1 + w] = pack2(y2, y2);
        d0[(c0 + 3) * RSTRD + 1 + w] = pack2(y3, y3);
        if (w == 0  && r > 0)  publish(sbase, 0, 1, r - 1, c0, y0, y1, y2, y3);
        if (w == 15 && r < 15) publish(sbase, 0, 0, r + 1, c0, y0, y1, y2, y3);
    }
    __syncthreads();

    int cnt0 = 0, cnt1 = 0;   // phase counters for bar[0]/bar[1] (edge lanes only)

    // ---- recurrence ----
    for (int h = 1; h < Hh; h++) {
        const int pprev = (h - 1) & 1;
        const int pcur  = h & 1;
        ull* rd = (pprev == 0) ? d0 : d1;   // row h-1
        ull* wr = (pcur  == 0) ? d0 : d1;   // row h

        // prefetch X for this row's outputs (hidden under conv)
        const float* xrow = Xb + h * Ww + wg;
        float xi0 = xrow[(c0 + 0) * HWs];
        float xi1 = xrow[(c0 + 1) * HWs];
        float xi2 = xrow[(c0 + 2) * HWs];
        float xi3 = xrow[(c0 + 3) * HWs];

        // edge lanes wait for neighbors' row h-1 halos (local mbarrier, HW sleep)
        if (w == 0 || w == 15) {
            int parity;
            if (pprev == 0) { parity = cnt0 & 1; cnt0++; }
            else            { parity = cnt1 & 1; cnt1++; }
            mbar_wait_cluster(sbase + OFF_BAR + (unsigned)pprev * 8u, parity);
        }

        ull a01 = b01, a23 = b23;
        const ull* xpl; int sl;
        const ull* xpr; int sr;
        const ull* xpc = rd + 1 + w;
        if (w == 0)  { xpl = sHalo + pprev * 128 + 0;  sl = 1; }
        else         { xpl = rd + w;                   sl = RSTRD; }
        if (w == 15) { xpr = sHalo + pprev * 128 + 64; sr = 1; }
        else         { xpr = rd + 2 + w;               sr = RSTRD; }
        const ulonglong2* kp =
            reinterpret_cast<const ulonglong2*>(wMain) + g * 192;

#pragma unroll 16
        for (int cin = 0; cin < Cc; cin++) {
            ull xll = *xpl;
            ull xcc = *xpc;
            ull xrr = *xpr;
            ulonglong2 K0 = kp[0];
            ulonglong2 K1 = kp[1];
            ulonglong2 K2 = kp[2];
            FMA2(a01, K0.x, xll); FMA2(a23, K0.y, xll);
            FMA2(a01, K1.x, xcc); FMA2(a23, K1.y, xcc);
            FMA2(a01, K2.x, xrr); FMA2(a23, K2.y, xrr);
            xpl += sl; xpc += RSTRD; xpr += sr; kp += 3;
        }

        float a0, a1, a2, a3;
        unpack2(a01, a0, a1);
        unpack2(a23, a2, a3);
        float y0 = xi0 + tanh_fast(a0);
        float y1 = xi1 + tanh_fast(a1);
        float y2 = xi2 + tanh_fast(a2);
        float y3 = xi3 + tanh_fast(a3);

        // push edges to neighbors ASAP (own values only — no intra-CTA sync needed)
        if (h < Hh - 1) {
            if (w == 0  && r > 0)  publish(sbase, pcur, 1, r - 1, c0, y0, y1, y2, y3);
            if (w == 15 && r < 15) publish(sbase, pcur, 0, r + 1, c0, y0, y1, y2, y3);
        }

        float* yrow = Yb + h * Ww + wg;
        yrow[(c0 + 0) * HWs] = y0;
        yrow[(c0 + 1) * HWs] = y1;
        yrow[(c0 + 2) * HWs] = y2;
        yrow[(c0 + 3) * HWs] = y3;

        wr[(c0 + 0) * RSTRD + 1 + w] = pack2(y0, y0);
        wr[(c0 + 1) * RSTRD + 1 + w] = pack2(y1, y1);
        wr[(c0 + 2) * RSTRD + 1 + w] = pack2(y2, y2);
        wr[(c0 + 3) * RSTRD + 1 + w] = pack2(y3, y3);

        __syncthreads();
    }

    cluster_sync_();   // no CTA exits while peers may still target its smem
}

// ==================== fallback kernel (proven 1289us path) ====================
#define FB_RSTR 20
#define FB_ROW_FLOATS (Cc * FB_RSTR)
#define FB_W_F4 (16 * Cc * 3)
#define FB_SMEM ((FB_ROW_FLOATS * 4) + (FB_W_F4 * 16))

__device__ float        g_halo[Bq][RB][2][2][Cc];
__device__ unsigned int g_flag[Bq][RB];

__device__ __forceinline__ float vload_f(const float* p) { return *((volatile const float*)p); }
__device__ __forceinline__ unsigned int vload_u(const unsigned int* p) { return *((volatile const unsigned int*)p); }

__global__ void __launch_bounds__(THREADS, 1)
spatial_conv_fallback(const float* __restrict__ X, const float* __restrict__ Wc,
                      const float* __restrict__ bc, float* __restrict__ Y)
{
    extern __shared__ float fsm[];
    float*  sRow = fsm;
    float4* wS4  = reinterpret_cast<float4*>(fsm + FB_ROW_FLOATS);

    const int tid = threadIdx.x;
    const int b = blockIdx.x >> 4, r = blockIdx.x & 15;
    const int w = tid & 15, g = tid >> 4, c0 = g * 4, wg = r * T_W + w;

    for (int idx = tid; idx < FB_W_F4; idx += THREADS) {
        int gg = idx / 192, rem = idx - gg * 192, cin = rem / 3, tap = rem - cin * 3;
        float4 v;
        v.x = Wc[((4 * gg + 0) * Cc + cin) * 3 + tap];
        v.y = Wc[((4 * gg + 1) * Cc + cin) * 3 + tap];
        v.z = Wc[((4 * gg + 2) * Cc + cin) * 3 + tap];
        v.w = Wc[((4 * gg + 3) * Cc + cin) * 3 + tap];
        wS4[idx] = v;
    }
    const float bz0 = bc[c0], bz1 = bc[c0 + 1], bz2 = bc[c0 + 2], bz3 = bc[c0 + 3];
    unsigned int base = 0;
    if (tid < 2) base = vload_u(&g_flag[b][r]);
    const float* Xb = X + b * CHW;
    float*       Yb = Y + b * CHW;
    {
        float y0 = Xb[(c0 + 0) * HWs + wg], y1 = Xb[(c0 + 1) * HWs + wg];
        float y2 = Xb[(c0 + 2) * HWs + wg], y3 = Xb[(c0 + 3) * HWs + wg];
        Yb[(c0 + 0) * HWs + wg] = y0; Yb[(c0 + 1) * HWs + wg] = y1;
        Yb[(c0 + 2) * HWs + wg] = y2; Yb[(c0 + 3) * HWs + wg] = y3;
        sRow[(c0 + 0) * FB_RSTR + 1 + w] = y0; sRow[(c0 + 1) * FB_RSTR + 1 + w] = y1;
        sRow[(c0 + 2) * FB_RSTR + 1 + w] = y2; sRow[(c0 + 3) * FB_RSTR + 1 + w] = y3;
        if (w == 0)  { float* hp = &g_halo[b][r][0][0][c0]; hp[0]=y0; hp[1]=y1; hp[2]=y2; hp[3]=y3; __threadfence(); }
        if (w == 15) { float* hp = &g_halo[b][r][1][0][c0]; hp[0]=y0; hp[1]=y1; hp[2]=y2; hp[3]=y3; __threadfence(); }
    }
    __syncthreads();
    if (tid == 0) {
        atomicExch(&g_flag[b][r], base + 1u);
        if (r > 0) { unsigned int t = base + 1u; while ((int)(vload_u(&g_flag[b][r - 1]) - t) < 0) {} }
    } else if (tid == 1) {
        if (r < 15) { unsigned int t = base + 1u; while ((int)(vload_u(&g_flag[b][r + 1]) - t) < 0) {} }
    }
    __syncthreads();
    if (tid < Cc) {
        float v = (r > 0) ? vload_f(&g_halo[b][r - 1][1][0][tid]) : 0.0f;
        sRow[tid * FB_RSTR + 0] = v;
    } else if (tid < 2 * Cc) {
        int ch = tid - Cc;
        float v = (r < 15) ? vload_f(&g_halo[b][r + 1][0][0][ch]) : 0.0f;
        sRow[ch * FB_RSTR + 17] = v;
    }
    __syncthreads();

    for (int h = 1; h < Hh; h++) {
        const float* xrow = Xb + h * Ww + wg;
        float xi0 = xrow[(c0 + 0) * HWs], xi1 = xrow[(c0 + 1) * HWs];
        float xi2 = xrow[(c0 + 2) * HWs], xi3 = xrow[(c0 + 3) * HWs];
        float a0 = bz0, a1 = bz1, a2 = bz2, a3 = bz3;
        const float*  xp = sRow + w;
        const float4* wp = wS4 + g * 192;
#pragma unroll 8
        for (int cin = 0; cin < Cc; cin++) {
            float xl = xp[0], xc = xp[1], xr = xp[2];
            float4 K0 = wp[0], K1 = wp[1], K2 = wp[2];
            a0 = fmaf(K0.x, xl, a0); a0 = fmaf(K1.x, xc, a0); a0 = fmaf(K2.x, xr, a0);
            a1 = fmaf(K0.y, xl, a1); a1 = fmaf(K1.y, xc, a1); a1 = fmaf(K2.y, xr, a1);
            a2 = fmaf(K0.z, xl, a2); a2 = fmaf(K1.z, xc, a2); a2 = fmaf(K2.z, xr, a2);
            a3 = fmaf(K0.w, xl, a3); a3 = fmaf(K1.w, xc, a3); a3 = fmaf(K2.w, xr, a3);
            xp += FB_RSTR; wp += 3;
        }
        float y0 = xi0 + tanh_fast(a0), y1 = xi1 + tanh_fast(a1);
        float y2 = xi2 + tanh_fast(a2), y3 = xi3 + tanh_fast(a3);
        float* yrow = Yb + h * Ww + wg;
        yrow[(c0 + 0) * HWs] = y0; yrow[(c0 + 1) * HWs] = y1;
        yrow[(c0 + 2) * HWs] = y2; yrow[(c0 + 3) * HWs] = y3;
        if (h == Hh - 1) { if (tid == 0) atomicExch(&g_flag[b][r], base + 256u); break; }
        __syncthreads();
        sRow[(c0 + 0) * FB_RSTR + 1 + w] = y0; sRow[(c0 + 1) * FB_RSTR + 1 + w] = y1;
        sRow[(c0 + 2) * FB_RSTR + 1 + w] = y2; sRow[(c0 + 3) * FB_RSTR + 1 + w] = y3;
        const int par = h & 1;
        if (w == 0)  { float* hp = &g_halo[b][r][0][par][c0]; hp[0]=y0; hp[1]=y1; hp[2]=y2; hp[3]=y3; __threadfence(); }
        if (w == 15) { float* hp = &g_halo[b][r][1][par][c0]; hp[0]=y0; hp[1]=y1; hp[2]=y2; hp[3]=y3; __threadfence(); }
        __syncthreads();
        if (tid == 0) {
            atomicExch(&g_flag[b][r], base + (unsigned)h + 1u);
            if (r > 0) { unsigned int t = base + (unsigned)h + 1u; while ((int)(vload_u(&g_flag[b][r - 1]) - t) < 0) {} }
        } else if (tid == 1) {
            if (r < 15) { unsigned int t = base + (unsigned)h + 1u; while ((int)(vload_u(&g_flag[b][r + 1]) - t) < 0) {} }
        }
        __syncthreads();
        if (tid < Cc) {
            float v = (r > 0) ? vload_f(&g_halo[b][r - 1][1][par][tid]) : 0.0f;
            sRow[tid * FB_RSTR + 0] = v;
        } else if (tid < 2 * Cc) {
            int ch = tid - Cc;
            float v = (r < 15) ? vload_f(&g_halo[b][r + 1][0][par][ch]) : 0.0f;
            sRow[ch * FB_RSTR + 17] = v;
        }
        __syncthreads();
    }
}

// ==================== launch ====================
extern "C" void kernel_launch(void* const* d_in, const int* in_sizes, int n_in,
                              void* d_out, int out_size)
{
    const float* X  = (const float*)d_in[0];
    const float* Wc = (const float*)d_in[1];
    const float* bc = (const float*)d_in[2];
    float*       Y  = (float*)d_out;
    (void)in_sizes; (void)n_in; (void)out_size;

    static int cluster_ok = -1;
    if (cluster_ok != 0) {
        cudaFuncSetAttribute(spatial_conv_cluster,
                             cudaFuncAttributeMaxDynamicSharedMemorySize, SMEM_BYTES);
        cudaFuncSetAttribute(spatial_conv_cluster,
                             cudaFuncAttributeNonPortableClusterSizeAllowed, 1);

        cudaLaunchConfig_t cfg = {};
        cfg.gridDim  = dim3(Bq * RB, 1, 1);
        cfg.blockDim = dim3(THREADS, 1, 1);
        cfg.dynamicSmemBytes = SMEM_BYTES;
        cfg.stream = 0;
        cudaLaunchAttribute attr[1];
        attr[0].id = cudaLaunchAttributeClusterDimension;
        attr[0].val.clusterDim.x = RB;
        attr[0].val.clusterDim.y = 1;
        attr[0].val.clusterDim.z = 1;
        cfg.attrs = attr;
        cfg.numAttrs = 1;

        cudaError_t e = cudaLaunchKernelEx(&cfg, spatial_conv_cluster, X, Wc, bc, Y);
        if (e == cudaSuccess) { cluster_ok = 1; return; }
        (void)cudaGetLastError();   // clear error, fall through to fallback
        cluster_ok = 0;
    }

    cudaFuncSetAttribute(spatial_conv_fallback,
                         cudaFuncAttributeMaxDynamicSharedMemorySize, FB_SMEM);
    spatial_conv_fallback<<<Bq * RB, THREADS, FB_SMEM>>>(X, Wc, bc, Y);
}

// round 10
// speedup vs baseline: 1.7532x; 1.7532x over previous
#include <cuda_runtime.h>
#include <math.h>
#include <stdint.h>

typedef unsigned long long ull;

// ---------------- problem constants ----------------
#define Bq   8
#define Cc   64
#define Hh   256
#define Ww   256
#define HWs  65536
#define CHW  4194304
#define RB   16          // CTAs per batch
#define T_W  16
#define THREADS 512      // 16 w-columns x 32 cout-pairs
#define RSTR 18          // floats per channel row: [0]=left halo, [1..16]=data, [17]=right halo

// smem map (bytes)
#define OFF_K    0                    // wK[gp][cin][4] ull : 32*64*4*8 = 65536
#define OFF_D0   65536                // row buf A: 64*18 floats = 4608
#define OFF_D1   70144                // row buf B: 4608
#define SMEM_BYTES 74752

// halo[b][r][side][parity][ch]: side0 = CTA r's leftmost col, side1 = rightmost
__device__ float        g_halo[Bq][RB][2][2][Cc];
// monotonic row counter per CTA; +256 per launch, uniform across CTAs
__device__ unsigned int g_flag[Bq][RB];

#define FMA2(acc, a, b) asm("fma.rn.f32x2 %0, %1, %2, %3;" : "=l"(acc) : "l"(a), "l"(b), "l"(acc))

__device__ __forceinline__ ull pack2(float lo, float hi) {
    ull r;
    asm("mov.b64 %0, {%1, %2};" : "=l"(r)
        : "r"(__float_as_uint(lo)), "r"(__float_as_uint(hi)));
    return r;
}
__device__ __forceinline__ ull dup2(float v) {
    ull r;
    asm("mov.b64 %0, {%1, %1};" : "=l"(r) : "r"(__float_as_uint(v)));
    return r;
}
__device__ __forceinline__ void unpack2(ull v, float& lo, float& hi) {
    unsigned int a, b2;
    asm("mov.b64 {%0, %1}, %2;" : "=r"(a), "=r"(b2) : "l"(v));
    lo = __uint_as_float(a); hi = __uint_as_float(b2);
}

__device__ __forceinline__ float tanh_fast(float x) {
    float ax = fabsf(x);
    float e  = __expf(2.0f * ax);
    float t  = 1.0f - 2.0f / (e + 1.0f);
    return copysignf(t, x);
}

__device__ __forceinline__ float vload_f(const float* p) { return *((volatile const float*)p); }
__device__ __forceinline__ unsigned int vload_u(const unsigned int* p) { return *((volatile const unsigned int*)p); }

__global__ void __launch_bounds__(THREADS, 1)
spatial_conv_kernel(const float* __restrict__ X,
                    const float* __restrict__ Wc,   // [64][64][3]
                    const float* __restrict__ bc,   // [64]
                    float* __restrict__ Y)
{
    extern __shared__ __align__(16) char smem[];
    ull*   wK = reinterpret_cast<ull*>(smem + OFF_K);     // [gp*64+cin]*4 + tap
    float* d0 = reinterpret_cast<float*>(smem + OFF_D0);  // row buffers
    float* d1 = reinterpret_cast<float*>(smem + OFF_D1);

    const int tid = threadIdx.x;
    const int b   = blockIdx.x >> 4;
    const int r   = blockIdx.x & 15;
    const int w   = tid & 15;          // local column
    const int gp  = tid >> 4;          // cout-pair 0..31
    const int c0  = gp * 2;            // couts c0, c0+1
    const int wg  = r * T_W + w;       // global column

    // ---- stage packed weights: wK[(gp*64+cin)*4 + tap] = (W[2gp][cin][tap], W[2gp+1][cin][tap]) ----
    for (int idx = tid; idx < 32 * Cc; idx += THREADS) {
        int g2  = idx >> 6;
        int cin = idx & 63;
        const float* w0 = Wc + ((2 * g2 + 0) * Cc + cin) * 3;
        const float* w1 = Wc + ((2 * g2 + 1) * Cc + cin) * 3;
        ull* dst = wK + (size_t)idx * 4;
        dst[0] = pack2(w0[0], w1[0]);
        dst[1] = pack2(w0[1], w1[1]);
        dst[2] = pack2(w0[2], w1[2]);
        dst[3] = 0ull;
    }
    // zero sentinels in both row buffers (edge CTAs keep them zero forever)
    for (int c = tid; c < Cc; c += THREADS) {
        d0[c * RSTR + 0]  = 0.0f; d0[c * RSTR + 17] = 0.0f;
        d1[c * RSTR + 0]  = 0.0f; d1[c * RSTR + 17] = 0.0f;
    }

    const ull bz = pack2(bc[c0], bc[c0 + 1]);

    unsigned int base = 0;
    if (tid < 2) base = vload_u(&g_flag[b][r]);

    const float* Xb = X + b * CHW;
    float*       Yb = Y + b * CHW;

    // ---- row 0: Y[0] = X[0] ----
    {
        float y0 = Xb[(c0 + 0) * HWs + wg];
        float y1 = Xb[(c0 + 1) * HWs + wg];
        Yb[(c0 + 0) * HWs + wg] = y0;
        Yb[(c0 + 1) * HWs + wg] = y1;
        d0[(c0 + 0) * RSTR + 1 + w] = y0;
        d0[(c0 + 1) * RSTR + 1 + w] = y1;
        if (w == 0) {
            float* hp = &g_halo[b][r][0][0][c0];
            hp[0] = y0; hp[1] = y1;
            __threadfence();
        }
        if (w == 15) {
            float* hp = &g_halo[b][r][1][0][c0];
            hp[0] = y0; hp[1] = y1;
            __threadfence();
        }
    }
    __syncthreads();
    if (tid == 0) {
        atomicExch(&g_flag[b][r], base + 1u);
        if (r > 0) { unsigned int t = base + 1u;
            while ((int)(vload_u(&g_flag[b][r - 1]) - t) < 0) {} }
    } else if (tid == 1) {
        if (r < 15) { unsigned int t = base + 1u;
            while ((int)(vload_u(&g_flag[b][r + 1]) - t) < 0) {} }
    }
    __syncthreads();
    if (tid < Cc) {
        float v = (r > 0) ? vload_f(&g_halo[b][r - 1][1][0][tid]) : 0.0f;
        d0[tid * RSTR + 0] = v;
    } else if (tid < 2 * Cc) {
        int ch = tid - Cc;
        float v = (r < 15) ? vload_f(&g_halo[b][r + 1][0][0][ch]) : 0.0f;
        d0[ch * RSTR + 17] = v;
    }
    __syncthreads();

    // ---- recurrence ----
    for (int h = 1; h < Hh; h++) {
        float* rd = ((h - 1) & 1) ? d1 : d0;   // row h-1
        float* wr = (h & 1) ? d1 : d0;         // row h

        // prefetch X for this row's outputs (hidden under the conv)
        const float* xrow = Xb + h * Ww + wg;
        float xi0 = xrow[(c0 + 0) * HWs];
        float xi1 = xrow[(c0 + 1) * HWs];

        ull a = bz;
        const float* xs = rd + w;                 // xs[0]=w-1, xs[1]=w, xs[2]=w+1
        const ull*   kp = wK + (size_t)gp * (Cc * 4);
#pragma unroll 8
        for (int cin = 0; cin < Cc; cin++) {
            float xl = xs[0];
            float xc = xs[1];
            float xr = xs[2];
            ulonglong2 Kab = *reinterpret_cast<const ulonglong2*>(kp);  // taps 0,1
            ull        Kc  = kp[2];                                     // tap 2
            FMA2(a, Kab.x, dup2(xl));
            FMA2(a, Kab.y, dup2(xc));
            FMA2(a, Kc,    dup2(xr));
            xs += RSTR;
            kp += 4;
        }

        float a0, a1;
        unpack2(a, a0, a1);
        float y0 = xi0 + tanh_fast(a0);
        float y1 = xi1 + tanh_fast(a1);

        float* yrow = Yb + h * Ww + wg;
        yrow[(c0 + 0) * HWs] = y0;
        yrow[(c0 + 1) * HWs] = y1;

        // write row h into the OTHER buffer (no hazard with rd)
        wr[(c0 + 0) * RSTR + 1 + w] = y0;
        wr[(c0 + 1) * RSTR + 1 + w] = y1;

        const int par = h & 1;
        if (w == 0) {
            float* hp = &g_halo[b][r][0][par][c0];
            hp[0] = y0; hp[1] = y1;
            __threadfence();
        }
        if (w == 15) {
            float* hp = &g_halo[b][r][1][par][c0];
            hp[0] = y0; hp[1] = y1;
            __threadfence();
        }

        if (h == Hh - 1) {
            if (tid == 0) atomicExch(&g_flag[b][r], base + 256u);  // launch invariant
            break;
        }

        __syncthreads();   // halo STGs + wr stores done CTA-wide

        if (tid == 0) {
            atomicExch(&g_flag[b][r], base + (unsigned)h + 1u);
            if (r > 0) { unsigned int t = base + (unsigned)h + 1u;
                while ((int)(vload_u(&g_flag[b][r - 1]) - t) < 0) {} }
        } else if (tid == 1) {
            if (r < 15) { unsigned int t = base + (unsigned)h + 1u;
                while ((int)(vload_u(&g_flag[b][r + 1]) - t) < 0) {} }
        }
        __syncthreads();

        // pull neighbor halos for row h into wr sentinels (volatile: parity slots recur)
        if (tid < Cc) {
            float v = (r > 0) ? vload_f(&g_halo[b][r - 1][1][par][tid]) : 0.0f;
            wr[tid * RSTR + 0] = v;
        } else if (tid < 2 * Cc) {
            int ch = tid - Cc;
            float v = (r < 15) ? vload_f(&g_halo[b][r + 1][0][par][ch]) : 0.0f;
            wr[ch * RSTR + 17] = v;
        }
        __syncthreads();
    }
}

extern "C" void kernel_launch(void* const* d_in, const int* in_sizes, int n_in,
                              void* d_out, int out_size)
{
    const float* X  = (const float*)d_in[0];
    const float* Wc = (const float*)d_in[1];
    const float* bc = (const float*)d_in[2];
    float*       Y  = (float*)d_out;
    (void)in_sizes; (void)n_in; (void)out_size;

    cudaFuncSetAttribute(spatial_conv_kernel,
                         cudaFuncAttributeMaxDynamicSharedMemorySize, SMEM_BYTES);

    spatial_conv_kernel<<<Bq * RB, THREADS, SMEM_BYTES>>>(X, Wc, bc, Y);
}

// round 13
// speedup vs baseline: 2.0921x; 1.1933x over previous
#include <cuda_runtime.h>
#include <math.h>

// Problem constants
#define Bq   8
#define Cc   64
#define Hh   256
#define Ww   256
#define HWs  65536        // H*W
#define CHW  4194304      // C*H*W
#define CTAS_PER_BATCH 16
#define T_W  16           // w columns per CTA
#define GROUPS 16         // cout groups (4 couts each)
#define THREADS 256
#define RSTR 20           // smem floats per channel row: [0]=halo, [1..16]=data, [17]=halo, pad
#define ROW_SMEM_FLOATS (Cc * RSTR)                     // 1280
#define W_SMEM_F4       (Cc * GROUPS * 3)               // 3072 float4 = 48 KB, [cin][g][tap]
#define SMEM_BYTES ((ROW_SMEM_FLOATS * 4) + (W_SMEM_F4 * 16))

// halo[b][r][side][parity][ch] : side 0 = CTA r's leftmost column, side 1 = rightmost
__device__ float        g_halo[Bq][CTAS_PER_BATCH][2][2][Cc];
// monotonic "rows completed" counter per CTA; +256 per launch, uniform across CTAs
__device__ unsigned int g_flag[Bq][CTAS_PER_BATCH];

// MUFU-free tanh: exp via FFMA-only 2^x, reciprocal via Newton from bit-trick seed.
// |abs error| ~1e-6; no EX2/RCP -> keeps the MUFU pipe (rt=8/SMSP) empty.
__device__ __forceinline__ float tanh_fast(float x) {
    float t = fminf(2.0f * fabsf(x), 24.0f);          // tanh saturates long before 12
    float s = t * 1.4426950408889634f;                // t * log2(e), s in [0, 34.7]
    float kf = s + 12582912.0f;                       // round to nearest int (2^23*1.5 magic)
    int   n  = __float_as_int(kf) - 0x4B400000;       // integer part, exact
    float f  = s - (kf - 12582912.0f);                // fractional part, |f| <= 0.5
    // 2^f via degree-6 polynomial (Taylor in f*ln2), rel err ~1e-7
    float p = 1.5423431e-4f;
    p = fmaf(p, f, 1.3333558e-3f);
    p = fmaf(p, f, 9.6181291e-3f);
    p = fmaf(p, f, 5.5504109e-2f);
    p = fmaf(p, f, 2.4022651e-1f);
    p = fmaf(p, f, 6.9314718e-1f);
    p = fmaf(p, f, 1.0f);
    float e = __int_as_float(__float_as_int(p) + (n << 23));   // e = exp(t) = 2^n * 2^f
    float u = e + 1.0f;
    // r = 1/u : bit-trick seed (~12% err) + 3 Newton iterations -> ~4e-8
    float r = __int_as_float(0x7EF311C3 - __float_as_int(u));
    r = r * fmaf(-u, r, 2.0f);
    r = r * fmaf(-u, r, 2.0f);
    r = r * fmaf(-u, r, 2.0f);
    return copysignf(fmaf(-2.0f, r, 1.0f), x);        // tanh = 1 - 2/(e+1)
}

__device__ __forceinline__ float vload_f(const float* p) {
    return *((volatile const float*)p);
}
__device__ __forceinline__ unsigned int vload_u(const unsigned int* p) {
    return *((volatile const unsigned int*)p);
}

__global__ void __launch_bounds__(THREADS, 1)
spatial_conv_kernel(const float* __restrict__ X,
                    const float* __restrict__ Wc,   // [64][64][3]
                    const float* __restrict__ bc,   // [64]
                    float* __restrict__ Y)
{
    extern __shared__ float smem[];
    float*  sRow = smem;                                              // [64][RSTR]
    float4* wS4  = reinterpret_cast<float4*>(smem + ROW_SMEM_FLOATS); // [cin][g][tap]

    const int tid = threadIdx.x;
    const int b   = blockIdx.x >> 4;
    const int r   = blockIdx.x & 15;
    const int w   = tid & 15;          // local column 0..15
    const int g   = tid >> 4;          // cout group 0..15
    const int c0  = g * 4;             // first of 4 couts
    const int wg  = r * T_W + w;       // global column

    // ---- stage weights: wS4[(cin*16 + g)*3 + tap] = K_tap for couts 4g..4g+3 ----
    // [cin][g][tap] layout: the two g-halves of a warp sit 48 B apart -> different
    // banks -> every weight LDS.128 is a single conflict-free wavefront.
    for (int idx = tid; idx < W_SMEM_F4; idx += THREADS) {
        int cin = idx / 48;
        int rem = idx - cin * 48;
        int gg  = rem / 3;
        int tap = rem - gg * 3;
        float4 v;
        v.x = Wc[((4 * gg + 0) * Cc + cin) * 3 + tap];
        v.y = Wc[((4 * gg + 1) * Cc + cin) * 3 + tap];
        v.z = Wc[((4 * gg + 2) * Cc + cin) * 3 + tap];
        v.w = Wc[((4 * gg + 3) * Cc + cin) * 3 + tap];
        wS4[idx] = v;
    }
    const float bz0 = bc[c0 + 0];
    const float bz1 = bc[c0 + 1];
    const float bz2 = bc[c0 + 2];
    const float bz3 = bc[c0 + 3];

    unsigned int base = 0;
    if (tid < 2) base = vload_u(&g_flag[b][r]);

    const float* Xb = X + b * CHW;
    float*       Yb = Y + b * CHW;

    // ---- row 0: Y[0] = X[0] ----
    {
        float y0 = Xb[(c0 + 0) * HWs + wg];
        float y1 = Xb[(c0 + 1) * HWs + wg];
        float y2 = Xb[(c0 + 2) * HWs + wg];
        float y3 = Xb[(c0 + 3) * HWs + wg];
        Yb[(c0 + 0) * HWs + wg] = y0;
        Yb[(c0 + 1) * HWs + wg] = y1;
        Yb[(c0 + 2) * HWs + wg] = y2;
        Yb[(c0 + 3) * HWs + wg] = y3;
        sRow[(c0 + 0) * RSTR + 1 + w] = y0;
        sRow[(c0 + 1) * RSTR + 1 + w] = y1;
        sRow[(c0 + 2) * RSTR + 1 + w] = y2;
        sRow[(c0 + 3) * RSTR + 1 + w] = y3;
        if (w == 0) {
            float* hp = &g_halo[b][r][0][0][c0];
            hp[0] = y0; hp[1] = y1; hp[2] = y2; hp[3] = y3;
            __threadfence();
        }
        if (w == 15) {
            float* hp = &g_halo[b][r][1][0][c0];
            hp[0] = y0; hp[1] = y1; hp[2] = y2; hp[3] = y3;
            __threadfence();
        }
    }
    __syncthreads();
    if (tid == 0) {
        atomicExch(&g_flag[b][r], base + 1u);
        if (r > 0) { unsigned int t = base + 1u;
            while ((int)(vload_u(&g_flag[b][r - 1]) - t) < 0) {} }
    } else if (tid == 1) {
        if (r < 15) { unsigned int t = base + 1u;
            while ((int)(vload_u(&g_flag[b][r + 1]) - t) < 0) {} }
    }
    __syncthreads();
    if (tid < Cc) {
        float v = (r > 0) ? vload_f(&g_halo[b][r - 1][1][0][tid]) : 0.0f;
        sRow[tid * RSTR + 0] = v;
    } else if (tid < 2 * Cc) {
        int ch = tid - Cc;
        float v = (r < 15) ? vload_f(&g_halo[b][r + 1][0][0][ch]) : 0.0f;
        sRow[ch * RSTR + 17] = v;
    }
    __syncthreads();

    // ---- recurrence ----
    for (int h = 1; h < Hh; h++) {
        // prefetch X for this row's outputs (hidden under the conv)
        const float* xrow = Xb + h * Ww + wg;
        float xi0 = xrow[(c0 + 0) * HWs];
        float xi1 = xrow[(c0 + 1) * HWs];
        float xi2 = xrow[(c0 + 2) * HWs];
        float xi3 = xrow[(c0 + 3) * HWs];

        float a0 = bz0, a1 = bz1, a2 = bz2, a3 = bz3;

        const float*  xp = sRow + w;          // [0]=w-1, [1]=w, [2]=w+1
        const float4* wp = wS4 + g * 3;       // [cin][g][tap], stride 48 per cin
#pragma unroll 8
        for (int cin = 0; cin < Cc; cin++) {
            float xl = xp[0];
            float xc = xp[1];
            float xr = xp[2];
            float4 K0 = wp[0];
            float4 K1 = wp[1];
            float4 K2 = wp[2];
            a0 = fmaf(K0.x, xl, a0); a0 = fmaf(K1.x, xc, a0); a0 = fmaf(K2.x, xr, a0);
            a1 = fmaf(K0.y, xl, a1); a1 = fmaf(K1.y, xc, a1); a1 = fmaf(K2.y, xr, a1);
            a2 = fmaf(K0.z, xl, a2); a2 = fmaf(K1.z, xc, a2); a2 = fmaf(K2.z, xr, a2);
            a3 = fmaf(K0.w, xl, a3); a3 = fmaf(K1.w, xc, a3); a3 = fmaf(K2.w, xr, a3);
            xp += RSTR;
            wp += 48;
        }

        float y0 = xi0 + tanh_fast(a0);
        float y1 = xi1 + tanh_fast(a1);
        float y2 = xi2 + tanh_fast(a2);
        float y3 = xi3 + tanh_fast(a3);

        float* yrow = Yb + h * Ww + wg;
        yrow[(c0 + 0) * HWs] = y0;
        yrow[(c0 + 1) * HWs] = y1;
        yrow[(c0 + 2) * HWs] = y2;
        yrow[(c0 + 3) * HWs] = y3;

        if (h == Hh - 1) {
            if (tid == 0) atomicExch(&g_flag[b][r], base + 256u);  // launch invariant
            break;
        }

        __syncthreads();   // everyone done reading sRow (row h-1)

        sRow[(c0 + 0) * RSTR + 1 + w] = y0;
        sRow[(c0 + 1) * RSTR + 1 + w] = y1;
        sRow[(c0 + 2) * RSTR + 1 + w] = y2;
        sRow[(c0 + 3) * RSTR + 1 + w] = y3;
        const int par = h & 1;
        if (w == 0) {
            float* hp = &g_halo[b][r][0][par][c0];
            hp[0] = y0; hp[1] = y1; hp[2] = y2; hp[3] = y3;
            __threadfence();
        }
        if (w == 15) {
            float* hp = &g_halo[b][r][1][par][c0];
            hp[0] = y0; hp[1] = y1; hp[2] = y2; hp[3] = y3;
            __threadfence();
        }
        __syncthreads();

        if (tid == 0) {
            atomicExch(&g_flag[b][r], base + (unsigned)h + 1u);
            if (r > 0) { unsigned int t = base + (unsigned)h + 1u;
                while ((int)(vload_u(&g_flag[b][r - 1]) - t) < 0) {} }
        } else if (tid == 1) {
            if (r < 15) { unsigned int t = base + (unsigned)h + 1u;
                while ((int)(vload_u(&g_flag[b][r + 1]) - t) < 0) {} }
        }
        __syncthreads();

        // pull neighbor halos for row h (volatile: parity slots recur in L1)
        if (tid < Cc) {
            float v = (r > 0) ? vload_f(&g_halo[b][r - 1][1][par][tid]) : 0.0f;
            sRow[tid * RSTR + 0] = v;
        } else if (tid < 2 * Cc) {
            int ch = tid - Cc;
            float v = (r < 15) ? vload_f(&g_halo[b][r + 1][0][par][ch]) : 0.0f;
            sRow[ch * RSTR + 17] = v;
        }
        __syncthreads();
    }
}

extern "C" void kernel_launch(void* const* d_in, const int* in_sizes, int n_in,
                              void* d_out, int out_size)
{
    const float* X  = (const float*)d_in[0];
    const float* Wc = (const float*)d_in[1];
    const float* bc = (const float*)d_in[2];
    float*       Y  = (float*)d_out;
    (void)in_sizes; (void)n_in; (void)out_size;

    cudaFuncSetAttribute(spatial_conv_kernel,
                         cudaFuncAttributeMaxDynamicSharedMemorySize, SMEM_BYTES);

    spatial_conv_kernel<<<Bq * CTAS_PER_BATCH, THREADS, SMEM_BYTES>>>(X, Wc, bc, Y);
}